// round 11
// baseline (speedup 1.0000x reference)
#include <cuda_runtime.h>
#include <cuda_bf16.h>
#include <math.h>

#define CELLN 14
#define NCLS  80
#define BPC   3
#define FEAT  95            // 80 + 3 + 12
#define CELLS2 196          // 14*14
#define PRED_PER_B 18620    // 196*95
#define CSF   32.0f
#define IMGF  448.0f
#define EPSF  1e-9f
#define INV_PI2_4 0.40528473456935109f   // 4/pi^2
#define MAXB  4096

__device__ float g_ssum[MAXB * CELLS2];   // per (batch,cell): class sum of squares
__device__ float g_conf[MAXB];            // per-batch conf sumsq (reset by consumer)
__device__ float g_accum = 0.0f;          // global loss accumulator (reset by last block)
__device__ int   g_count = 0;             // obj-kernel block arrivals (reset by last block)

// ---------------------------------------------------------------------------
// Kernel A (stats): warp per 2 cells, trip count 1 — the proven 5.6 TB/s
// streaming shape. Per-cell class sumsq -> g_ssum; per-batch conf sumsq via
// spread atomicAdd (1024 addresses, fire-and-forget, hidden under the stream).
// ---------------------------------------------------------------------------
__global__ __launch_bounds__(256)
void stats_kernel(const float* __restrict__ P, int ncells)
{
    const int wg   = (blockIdx.x * 256 + threadIdx.x) >> 5;
    const int lane = threadIdx.x & 31;
    const int c0 = wg * 2;
    if (c0 >= ncells) return;                 // whole warp exits together

    const float* p0 = P + (size_t)c0 * FEAT;
    const float* p1 = p0 + FEAT;
    const float a0 = p0[lane], b0 = p0[lane + 32], q0 = (lane < 31) ? p0[lane + 64] : 0.0f;
    const float a1 = p1[lane], b1 = p1[lane + 32], q1 = (lane < 31) ? p1[lane + 64] : 0.0f;

    float cls0 = a0 * a0 + b0 * b0;
    float cls1 = a1 * a1 + b1 * b1;
    float conf = 0.0f;
    const float q02 = q0 * q0, q12 = q1 * q1;
    if (lane < 16)      { cls0 += q02;  cls1 += q12; }   // feats 64..79: class
    else if (lane < 19) { conf  = q02 + q12; }           // feats 80..82: confidence

    #pragma unroll
    for (int off = 16; off; off >>= 1) {
        cls0 += __shfl_xor_sync(0xFFFFFFFFu, cls0, off);
        cls1 += __shfl_xor_sync(0xFFFFFFFFu, cls1, off);
        conf += __shfl_xor_sync(0xFFFFFFFFu, conf, off);
    }
    if (lane == 0) {
        g_ssum[c0]     = cls0;
        g_ssum[c0 + 1] = cls1;                // c0 even, 196 even -> same batch
        atomicAdd(&g_conf[c0 / CELLS2], conf);
    }
}

// ---------------------------------------------------------------------------
// Kernel B (obj): ONE THREAD per (batch,object). All lanes useful, no shfl
// trees for the mask sum; CIoU over the 3 boxes computed serially per thread.
// o==0 thread folds in the noobject term 0.25*conf*nobj and resets g_conf.
// Block-reduce -> atomicAdd scalar; last block finalizes out.
// ---------------------------------------------------------------------------
__global__ __launch_bounds__(256)
void obj_kernel(const float* __restrict__ P,
                const float* __restrict__ labels,
                const int*   __restrict__ objects_num,
                float* __restrict__ out, int B, int M, int nblocks)
{
    __shared__ float swarp[8];
    __shared__ int   s_last;

    const int tid  = threadIdx.x;
    const int lane = tid & 31;
    const int wid  = tid >> 5;
    const int g    = blockIdx.x * 256 + tid;

    float loss = 0.0f;
    if (g < B * M) {
        const int b = g / M;
        const int o = g - b * M;
        int nobj = objects_num[b];
        if (nobj > M) nobj = M;

        if (o == 0) {
            const float cv = g_conf[b];
            g_conf[b] = 0.0f;                 // reset for next graph replay
            loss += 0.25f * cv * (float)nobj; // noobject full-grid term x nobj
        }

        if (o < nobj) {
            const float* lb = labels + (size_t)g * 5;
            const float x = lb[0], y = lb[1], w = lb[2], h = lb[3];
            const int   k = (int)lb[4];

            int ix0 = (int)floorf((x - 0.5f * w) * (1.0f / CSF));
            int ix1 = (int)fminf(ceilf((x + 0.5f * w) * (1.0f / CSF)), (float)CELLN);
            int iy0 = (int)floorf((y - 0.5f * h) * (1.0f / CSF));
            int iy1 = (int)fminf(ceilf((y + 0.5f * h) * (1.0f / CSF)), (float)CELLN);
            ix0 = max(ix0, 0); iy0 = max(iy0, 0);

            const float* pb = P + (size_t)b * PRED_PER_B;
            const float* ss = g_ssum + b * CELLS2;

            // class loss over the mask: sumsq - 2 p_k + 1 (independent L2 loads)
            float cls = 0.0f;
            for (int iy = iy0; iy < iy1; iy++) {
                const int base = iy * CELLN;
                #pragma unroll 2
                for (int ix = ix0; ix < ix1; ix++) {
                    const int cell = base + ix;
                    cls += __ldg(ss + cell) - 2.0f * __ldg(pb + cell * FEAT + k) + 1.0f;
                }
            }

            // center cell, 3 boxes serial
            const int cx = (int)floorf(x * (1.0f / CSF));
            const int cy = (int)floorf(y * (1.0f / CSF));
            const float* pc = pb + (cy * CELLN + cx) * FEAT;

            float ciou[BPC], pCr[BPC], pxr[BPC], pyr[BPC], pwr[BPC], phr[BPC];
            #pragma unroll
            for (int j = 0; j < BPC; j++) {
                const float pC = __ldg(pc + NCLS + j);
                const float* bx = pc + NCLS + BPC + 4 * j;
                const float px = __ldg(bx + 0) * CSF + (float)cx * CSF;
                const float py = __ldg(bx + 1) * CSF + (float)cy * CSF;
                const float pw = __ldg(bx + 2) * IMGF;
                const float ph = __ldg(bx + 3) * IMGF;

                // CIoU exactly per reference (incl. centers-vs-widths enclose quirk)
                const float x11 = px - 0.5f * pw, x12 = px + 0.5f * pw;
                const float y11 = py - 0.5f * ph, y12 = py + 0.5f * ph;
                const float x21 = x - 0.5f * w,   x22 = x + 0.5f * w;
                const float y21 = y - 0.5f * h,   y22 = y + 0.5f * h;
                const float iw = fmaxf(fminf(x12, x22) - fmaxf(x11, x21), 0.0f);
                const float ih = fmaxf(fminf(y12, y22) - fmaxf(y11, y21), 0.0f);
                const float inter = iw * ih;
                const float uni = pw * ph + w * h - inter;
                const float iou = inter / (uni + EPSF);
                const float cd  = (px - x) * (px - x) + (py - y) * (py - y);
                const float el = fminf(px, x), er = fmaxf(pw, w);
                const float et = fminf(py, y), eb = fmaxf(ph, h);
                const float ed = (er - el) * (er - el) + (eb - et) * (eb - et);
                const float da = atanf(w / (h + EPSF)) - atanf(pw / (ph + EPSF));
                const float v  = INV_PI2_4 * da * da;
                const float alpha = v / (1.0f - iou + v + EPSF);
                ciou[j] = iou - cd / (ed + EPSF) - alpha * v;
                pCr[j] = pC; pxr[j] = px; pyr[j] = py; pwr[j] = pw; phr[j] = ph;
            }
            const float m = fmaxf(ciou[0], fmaxf(ciou[1], ciou[2]));

            float contrib = 0.0f;
            #pragma unroll
            for (int j = 0; j < BPC; j++) {
                if (ciou[j] >= m) {           // reference tie semantics: all at max
                    const float d = pCr[j] - ciou[j];
                    contrib += 0.5f * d * d;               // object loss
                    contrib -= 0.25f * pCr[j] * pCr[j];    // removed from noobject
                    const float dx = (pxr[j] - x) * (1.0f / CSF);
                    const float dy = (pyr[j] - y) * (1.0f / CSF);
                    const float swp = sqrtf(fminf(fmaxf(pwr[j], 0.0f), IMGF));
                    const float shp = sqrtf(fminf(fmaxf(phr[j], 0.0f), IMGF));
                    const float dw = swp - sqrtf(fabsf(w));
                    const float dh = shp - sqrtf(fabsf(h));
                    contrib += 5.0f * (0.5f * dx * dx + 0.5f * dy * dy
                                       + (0.5f * dw * dw) * (1.0f / IMGF)
                                       + (0.5f * dh * dh) * (1.0f / IMGF));
                }
            }
            loss += 0.5f * cls + contrib;
        }
    }

    // block reduce -> one atomicAdd per block
    #pragma unroll
    for (int off = 16; off; off >>= 1)
        loss += __shfl_xor_sync(0xFFFFFFFFu, loss, off);
    if (lane == 0) swarp[wid] = loss;
    __syncthreads();
    if (tid == 0) {
        float s = 0.0f;
        #pragma unroll
        for (int i = 0; i < 8; i++) s += swarp[i];
        atomicAdd(&g_accum, s);
        __threadfence();
        s_last = (atomicAdd(&g_count, 1) == nblocks - 1);
    }
    __syncthreads();

    if (s_last && tid == 0) {
        __threadfence();                     // acquire all g_accum adds
        out[0] = g_accum / (float)B;
        g_accum = 0.0f;                      // reset for next graph replay
        g_count = 0;
    }
}

extern "C" void kernel_launch(void* const* d_in, const int* in_sizes, int n_in,
                              void* d_out, int out_size)
{
    const float* predicts = (const float*)d_in[0];
    const float* labels   = (const float*)d_in[1];
    const int*   objnum   = (const int*)d_in[2];
    float* out = (float*)d_out;

    const int B = in_sizes[2];
    const int M = in_sizes[1] / (B * 5);
    const int ncells = B * CELLS2;

    const int gridA = ((ncells + 1) / 2 + 7) / 8;   // warp per 2 cells
    const int gridB = (B * M + 255) / 256;          // thread per (b,o)

    stats_kernel<<<gridA, 256>>>(predicts, ncells);
    obj_kernel<<<gridB, 256>>>(predicts, labels, objnum, out, B, M, gridB);
}

// round 13
// speedup vs baseline: 1.0227x; 1.0227x over previous
#include <cuda_runtime.h>
#include <cuda_bf16.h>
#include <math.h>

#define CELLN 14
#define NCLS  80
#define BPC   3
#define FEAT  95            // 80 + 3 + 12
#define CELLS2 196          // 14*14
#define PRED_PER_B 18620    // 196*95
#define CSF   32.0f
#define IMGF  448.0f
#define EPSF  1e-9f
#define INV_PI2_4 0.40528473456935109f   // 4/pi^2
#define MAXB  4096

__device__ float g_ssum[MAXB * CELLS2];   // per (batch,cell): class sum of squares
__device__ float g_conf[MAXB];            // per-batch conf sumsq (reset by consumer)
__device__ float g_accum = 0.0f;          // global loss accumulator (reset by last block)
__device__ int   g_count = 0;             // obj-kernel block arrivals (reset by last block)

// ---------------------------------------------------------------------------
// Kernel A (stats): warp per 2 cells, trip count 1 — the proven 5.6 TB/s
// streaming shape (unchanged).
// ---------------------------------------------------------------------------
__global__ __launch_bounds__(256)
void stats_kernel(const float* __restrict__ P, int ncells)
{
    const int wg   = (blockIdx.x * 256 + threadIdx.x) >> 5;
    const int lane = threadIdx.x & 31;
    const int c0 = wg * 2;
    if (c0 >= ncells) return;                 // warp-uniform exit

    const float* p0 = P + (size_t)c0 * FEAT;
    const float* p1 = p0 + FEAT;
    const float a0 = p0[lane], b0 = p0[lane + 32], q0 = (lane < 31) ? p0[lane + 64] : 0.0f;
    const float a1 = p1[lane], b1 = p1[lane + 32], q1 = (lane < 31) ? p1[lane + 64] : 0.0f;

    float cls0 = a0 * a0 + b0 * b0;
    float cls1 = a1 * a1 + b1 * b1;
    float conf = 0.0f;
    const float q02 = q0 * q0, q12 = q1 * q1;
    if (lane < 16)      { cls0 += q02;  cls1 += q12; }   // feats 64..79: class
    else if (lane < 19) { conf  = q02 + q12; }           // feats 80..82: confidence

    #pragma unroll
    for (int off = 16; off; off >>= 1) {
        cls0 += __shfl_xor_sync(0xFFFFFFFFu, cls0, off);
        cls1 += __shfl_xor_sync(0xFFFFFFFFu, cls1, off);
        conf += __shfl_xor_sync(0xFFFFFFFFu, conf, off);
    }
    if (lane == 0) {
        g_ssum[c0]     = cls0;
        g_ssum[c0 + 1] = cls1;
        atomicAdd(&g_conf[c0 / CELLS2], conf);
    }
}

// ---------------------------------------------------------------------------
// Kernel B (obj): FOUR threads per (batch,object). ALL shuffles are
// warp-uniform — every thread executes the full body; validity is applied
// as a multiplicative flag at the end (labels are valid for all o < M).
// ---------------------------------------------------------------------------
__global__ __launch_bounds__(256)
void obj_kernel(const float* __restrict__ P,
                const float* __restrict__ labels,
                const int*   __restrict__ objects_num,
                float* __restrict__ out, int B, int M, int nblocks)
{
    __shared__ float swarp[8];
    __shared__ int   s_last;

    const int tid  = threadIdx.x;
    const int lane = tid & 31;
    const int wid  = tid >> 5;
    const int gt   = blockIdx.x * 256 + tid;
    const int gr   = gt >> 2;                       // raw (batch,object) pair id
    const int sub  = gt & 3;                        // 0..3 within group
    const int nwork = B * M;
    const bool inrange = (gr < nwork);
    const int g    = inrange ? gr : (nwork - 1);    // clamped (safety; uniform shape)

    const int b = g / M;
    const int o = g - b * M;
    int nobj = objects_num[b];
    if (nobj > M) nobj = M;
    const bool valid = inrange && (o < nobj);

    float loss = 0.0f;
    if (inrange && o == 0 && sub == 0) {
        const float cv = g_conf[b];
        g_conf[b] = 0.0f;                     // reset for next graph replay
        loss += 0.25f * cv * (float)nobj;     // noobject full-grid term x nobj
    }

    // ---- full body executed by ALL threads (labels valid for all o < M) ----
    const float* lb = labels + (size_t)g * 5;
    const float x = lb[0], y = lb[1], w = lb[2], h = lb[3];
    const int   k = (int)lb[4];

    int ix0 = (int)floorf((x - 0.5f * w) * (1.0f / CSF));
    int ix1 = (int)fminf(ceilf((x + 0.5f * w) * (1.0f / CSF)), (float)CELLN);
    int iy0 = (int)floorf((y - 0.5f * h) * (1.0f / CSF));
    int iy1 = (int)fminf(ceilf((y + 0.5f * h) * (1.0f / CSF)), (float)CELLN);
    ix0 = max(ix0, 0); iy0 = max(iy0, 0);
    const int nx  = max(0, ix1 - ix0);
    const int ny  = max(0, iy1 - iy0);
    const int cnt = nx * ny;

    const float* pb = P + (size_t)b * PRED_PER_B;
    const float* ss = g_ssum + b * CELLS2;

    // class loss over mask, stride 4 across the group, unrolled 7 slots
    float cls = 0.0f;
    #pragma unroll
    for (int jj = 0; jj < 7; jj++) {
        const int t = sub + jj * 4;
        if (t < cnt) {
            const int iy = iy0 + t / nx;
            const int ix = ix0 + t % nx;
            const int cell = iy * CELLN + ix;
            cls += __ldg(ss + cell) - 2.0f * __ldg(pb + cell * FEAT + k) + 1.0f;
        }
    }
    for (int t = sub + 28; t < cnt; t += 4) {          // rare large-mask tail
        const int iy = iy0 + t / nx;
        const int ix = ix0 + t % nx;
        const int cell = iy * CELLN + ix;
        cls += __ldg(ss + cell) - 2.0f * __ldg(pb + cell * FEAT + k) + 1.0f;
    }
    // combine cls across the 4-thread group (warp-uniform shuffles)
    cls += __shfl_xor_sync(0xFFFFFFFFu, cls, 1);
    cls += __shfl_xor_sync(0xFFFFFFFFu, cls, 2);

    // center cell: sub-thread j (< 3) handles box j
    const int cx = (int)floorf(x * (1.0f / CSF));
    const int cy = (int)floorf(y * (1.0f / CSF));
    const float* pc = pb + (cy * CELLN + cx) * FEAT;
    const int jb = (sub < BPC) ? sub : 0;              // sub 3 mirrors box 0 (discarded)

    const float pC = __ldg(pc + NCLS + jb);
    const float* bx = pc + NCLS + BPC + 4 * jb;
    const float px = __ldg(bx + 0) * CSF + (float)cx * CSF;
    const float py = __ldg(bx + 1) * CSF + (float)cy * CSF;
    const float pw = __ldg(bx + 2) * IMGF;
    const float ph = __ldg(bx + 3) * IMGF;

    // CIoU exactly per reference (incl. centers-vs-widths enclose quirk)
    float ciou;
    {
        const float x11 = px - 0.5f * pw, x12 = px + 0.5f * pw;
        const float y11 = py - 0.5f * ph, y12 = py + 0.5f * ph;
        const float x21 = x - 0.5f * w,   x22 = x + 0.5f * w;
        const float y21 = y - 0.5f * h,   y22 = y + 0.5f * h;
        const float iw = fmaxf(fminf(x12, x22) - fmaxf(x11, x21), 0.0f);
        const float ih = fmaxf(fminf(y12, y22) - fmaxf(y11, y21), 0.0f);
        const float inter = iw * ih;
        const float uni = pw * ph + w * h - inter;
        const float iou = inter / (uni + EPSF);
        const float cd  = (px - x) * (px - x) + (py - y) * (py - y);
        const float el = fminf(px, x), er = fmaxf(pw, w);
        const float et = fminf(py, y), eb = fmaxf(ph, h);
        const float ed = (er - el) * (er - el) + (eb - et) * (eb - et);
        const float da = atanf(w / (h + EPSF)) - atanf(pw / (ph + EPSF));
        const float v  = INV_PI2_4 * da * da;
        const float alpha = v / (1.0f - iou + v + EPSF);
        ciou = iou - cd / (ed + EPSF) - alpha * v;
    }
    const float my_ciou = (sub < BPC) ? ciou : -1e30f;

    // group max over the 3 boxes (warp-uniform shuffles)
    float m = my_ciou;
    m = fmaxf(m, __shfl_xor_sync(0xFFFFFFFFu, m, 1));
    m = fmaxf(m, __shfl_xor_sync(0xFFFFFFFFu, m, 2));

    float contrib = 0.0f;
    if (sub < BPC && my_ciou >= m) {          // no shuffles inside
        const float d = pC - ciou;
        contrib += 0.5f * d * d;              // object loss
        contrib -= 0.25f * pC * pC;           // removed from noobject term
        const float dx = (px - x) * (1.0f / CSF);
        const float dy = (py - y) * (1.0f / CSF);
        const float swp = sqrtf(fminf(fmaxf(pw, 0.0f), IMGF));
        const float shp = sqrtf(fminf(fmaxf(ph, 0.0f), IMGF));
        const float dw = swp - sqrtf(fabsf(w));
        const float dh = shp - sqrtf(fabsf(h));
        contrib += 5.0f * (0.5f * dx * dx + 0.5f * dy * dy
                           + (0.5f * dw * dw) * (1.0f / IMGF)
                           + (0.5f * dh * dh) * (1.0f / IMGF));
    }
    contrib += __shfl_xor_sync(0xFFFFFFFFu, contrib, 1);
    contrib += __shfl_xor_sync(0xFFFFFFFFu, contrib, 2);

    if (valid && sub == 0)
        loss += 0.5f * cls + contrib;         // cls/contrib hold full group sums

    // block reduce -> one atomicAdd per block
    #pragma unroll
    for (int off = 16; off; off >>= 1)
        loss += __shfl_xor_sync(0xFFFFFFFFu, loss, off);
    if (lane == 0) swarp[wid] = loss;
    __syncthreads();
    if (tid == 0) {
        float s = 0.0f;
        #pragma unroll
        for (int i = 0; i < 8; i++) s += swarp[i];
        atomicAdd(&g_accum, s);
        __threadfence();
        s_last = (atomicAdd(&g_count, 1) == nblocks - 1);
    }
    __syncthreads();

    if (s_last && tid == 0) {
        __threadfence();
        out[0] = g_accum / (float)B;
        g_accum = 0.0f;                       // reset for next graph replay
        g_count = 0;
    }
}

extern "C" void kernel_launch(void* const* d_in, const int* in_sizes, int n_in,
                              void* d_out, int out_size)
{
    const float* predicts = (const float*)d_in[0];
    const float* labels   = (const float*)d_in[1];
    const int*   objnum   = (const int*)d_in[2];
    float* out = (float*)d_out;

    const int B = in_sizes[2];
    const int M = in_sizes[1] / (B * 5);
    const int ncells = B * CELLS2;

    const int gridA = ((ncells + 1) / 2 + 7) / 8;   // warp per 2 cells
    const int gridB = (B * M * 4 + 255) / 256;      // 4 threads per (b,o)

    stats_kernel<<<gridA, 256>>>(predicts, ncells);
    obj_kernel<<<gridB, 256>>>(predicts, labels, objnum, out, B, M, gridB);
}

// round 14
// speedup vs baseline: 1.7664x; 1.7273x over previous
#include <cuda_runtime.h>
#include <cuda_bf16.h>
#include <math.h>

#define CELLN 14
#define NCLS  80
#define BPC   3
#define FEAT  95            // 80 + 3 + 12
#define CELLS2 196          // 14*14
#define PRED_PER_B 18620    // 196*95
#define CSF   32.0f
#define IMGF  448.0f
#define EPSF  1e-9f
#define INV_PI2_4 0.40528473456935109f   // 4/pi^2
#define MAXB  4096
#define CPAD  32            // g_conf padding: 32 floats = 128B per batch

__device__ float g_ssum[MAXB * CELLS2];   // per (batch,cell): class sum of squares
__device__ float g_conf[MAXB * CPAD];     // per-batch conf sumsq, 128B stride (reset by consumer)
__device__ float g_accum = 0.0f;          // global loss accumulator (reset by last block)
__device__ int   g_count = 0;             // obj-kernel block arrivals (reset by last block)

// ---------------------------------------------------------------------------
// Kernel A (stats): warp per 2 cells, trip count 1 — proven 5.6 TB/s shape.
// Per-batch conf via atomicAdd to 128B-strided addresses (no line contention).
// ---------------------------------------------------------------------------
__global__ __launch_bounds__(256)
void stats_kernel(const float* __restrict__ P, int ncells)
{
    const int wg   = (blockIdx.x * 256 + threadIdx.x) >> 5;
    const int lane = threadIdx.x & 31;
    const int c0 = wg * 2;
    if (c0 >= ncells) return;                 // warp-uniform exit

    const float* p0 = P + (size_t)c0 * FEAT;
    const float* p1 = p0 + FEAT;
    const float a0 = p0[lane], b0 = p0[lane + 32], q0 = (lane < 31) ? p0[lane + 64] : 0.0f;
    const float a1 = p1[lane], b1 = p1[lane + 32], q1 = (lane < 31) ? p1[lane + 64] : 0.0f;

    float cls0 = a0 * a0 + b0 * b0;
    float cls1 = a1 * a1 + b1 * b1;
    float conf = 0.0f;
    const float q02 = q0 * q0, q12 = q1 * q1;
    if (lane < 16)      { cls0 += q02;  cls1 += q12; }   // feats 64..79: class
    else if (lane < 19) { conf  = q02 + q12; }           // feats 80..82: confidence

    #pragma unroll
    for (int off = 16; off; off >>= 1) {
        cls0 += __shfl_xor_sync(0xFFFFFFFFu, cls0, off);
        cls1 += __shfl_xor_sync(0xFFFFFFFFu, cls1, off);
        conf += __shfl_xor_sync(0xFFFFFFFFu, conf, off);
    }
    if (lane == 0) {
        g_ssum[c0]     = cls0;
        g_ssum[c0 + 1] = cls1;
        atomicAdd(&g_conf[(c0 / CELLS2) * CPAD], conf);   // 128B-strided target
    }
}

// ---------------------------------------------------------------------------
// Kernel B (obj): EIGHT threads per (batch,object) -> 7680 warps. Center-cell
// loads hoisted before the mask loop (overlapped round-trips). All shuffles
// warp-uniform; validity applied as a flag at the end.
// ---------------------------------------------------------------------------
__global__ __launch_bounds__(256)
void obj_kernel(const float* __restrict__ P,
                const float* __restrict__ labels,
                const int*   __restrict__ objects_num,
                float* __restrict__ out, int B, int M, int nblocks)
{
    __shared__ float swarp[8];
    __shared__ int   s_last;

    const int tid  = threadIdx.x;
    const int lane = tid & 31;
    const int wid  = tid >> 5;
    const int gt   = blockIdx.x * 256 + tid;
    const int gr   = gt >> 3;                       // (batch,object) pair id
    const int sub  = gt & 7;                        // 0..7 within group
    const int nwork = B * M;
    const bool inrange = (gr < nwork);
    const int g    = inrange ? gr : (nwork - 1);

    const int b = g / M;
    const int o = g - b * M;
    int nobj = objects_num[b];
    if (nobj > M) nobj = M;
    const bool valid = inrange && (o < nobj);

    float loss = 0.0f;
    if (inrange && o == 0 && sub == 0) {
        const float cv = g_conf[b * CPAD];
        g_conf[b * CPAD] = 0.0f;              // reset for next graph replay
        loss += 0.25f * cv * (float)nobj;     // noobject full-grid term x nobj
    }

    // ---- full body executed by ALL threads ----
    const float* lb = labels + (size_t)g * 5;
    const float x = lb[0], y = lb[1], w = lb[2], h = lb[3];
    const int   k = (int)lb[4];

    // center cell loads FIRST (independent -> overlap with mask loads)
    const int cx = (int)floorf(x * (1.0f / CSF));
    const int cy = (int)floorf(y * (1.0f / CSF));
    const float* pb = P + (size_t)b * PRED_PER_B;
    const float* pc = pb + (cy * CELLN + cx) * FEAT;
    const int jb = (sub < BPC) ? sub : 0;

    const float pC  = __ldg(pc + NCLS + jb);
    const float* bx = pc + NCLS + BPC + 4 * jb;
    const float bx0 = __ldg(bx + 0), bx1 = __ldg(bx + 1);
    const float bx2 = __ldg(bx + 2), bx3 = __ldg(bx + 3);

    int ix0 = (int)floorf((x - 0.5f * w) * (1.0f / CSF));
    int ix1 = (int)fminf(ceilf((x + 0.5f * w) * (1.0f / CSF)), (float)CELLN);
    int iy0 = (int)floorf((y - 0.5f * h) * (1.0f / CSF));
    int iy1 = (int)fminf(ceilf((y + 0.5f * h) * (1.0f / CSF)), (float)CELLN);
    ix0 = max(ix0, 0); iy0 = max(iy0, 0);
    const int nx  = max(0, ix1 - ix0);
    const int ny  = max(0, iy1 - iy0);
    const int cnt = nx * ny;

    const float* ss = g_ssum + b * CELLS2;

    // mask loop: stride 8 across group, 4 unrolled slots (cnt <= 25 always)
    float cls = 0.0f;
    #pragma unroll
    for (int jj = 0; jj < 4; jj++) {
        const int t = sub + jj * 8;
        if (t < cnt) {
            const int iy = iy0 + t / nx;
            const int ix = ix0 + t % nx;
            const int cell = iy * CELLN + ix;
            cls += __ldg(ss + cell) - 2.0f * __ldg(pb + cell * FEAT + k) + 1.0f;
        }
    }
    for (int t = sub + 32; t < cnt; t += 8) {          // safety tail (not taken)
        const int iy = iy0 + t / nx;
        const int ix = ix0 + t % nx;
        const int cell = iy * CELLN + ix;
        cls += __ldg(ss + cell) - 2.0f * __ldg(pb + cell * FEAT + k) + 1.0f;
    }
    cls += __shfl_xor_sync(0xFFFFFFFFu, cls, 1);
    cls += __shfl_xor_sync(0xFFFFFFFFu, cls, 2);
    cls += __shfl_xor_sync(0xFFFFFFFFu, cls, 4);

    const float px = bx0 * CSF + (float)cx * CSF;
    const float py = bx1 * CSF + (float)cy * CSF;
    const float pw = bx2 * IMGF;
    const float ph = bx3 * IMGF;

    // CIoU exactly per reference (incl. centers-vs-widths enclose quirk)
    float ciou;
    {
        const float x11 = px - 0.5f * pw, x12 = px + 0.5f * pw;
        const float y11 = py - 0.5f * ph, y12 = py + 0.5f * ph;
        const float x21 = x - 0.5f * w,   x22 = x + 0.5f * w;
        const float y21 = y - 0.5f * h,   y22 = y + 0.5f * h;
        const float iw = fmaxf(fminf(x12, x22) - fmaxf(x11, x21), 0.0f);
        const float ih = fmaxf(fminf(y12, y22) - fmaxf(y11, y21), 0.0f);
        const float inter = iw * ih;
        const float uni = pw * ph + w * h - inter;
        const float iou = inter / (uni + EPSF);
        const float cd  = (px - x) * (px - x) + (py - y) * (py - y);
        const float el = fminf(px, x), er = fmaxf(pw, w);
        const float et = fminf(py, y), eb = fmaxf(ph, h);
        const float ed = (er - el) * (er - el) + (eb - et) * (eb - et);
        const float da = atanf(w / (h + EPSF)) - atanf(pw / (ph + EPSF));
        const float v  = INV_PI2_4 * da * da;
        const float alpha = v / (1.0f - iou + v + EPSF);
        ciou = iou - cd / (ed + EPSF) - alpha * v;
    }
    const float my_ciou = (sub < BPC) ? ciou : -1e30f;

    // group max over 3 boxes (8-lane group: xor 1,2,4)
    float m = my_ciou;
    m = fmaxf(m, __shfl_xor_sync(0xFFFFFFFFu, m, 1));
    m = fmaxf(m, __shfl_xor_sync(0xFFFFFFFFu, m, 2));
    m = fmaxf(m, __shfl_xor_sync(0xFFFFFFFFu, m, 4));

    float contrib = 0.0f;
    if (sub < BPC && my_ciou >= m) {          // no shuffles inside
        const float d = pC - ciou;
        contrib += 0.5f * d * d;              // object loss
        contrib -= 0.25f * pC * pC;           // removed from noobject term
        const float dx = (px - x) * (1.0f / CSF);
        const float dy = (py - y) * (1.0f / CSF);
        const float swp = sqrtf(fminf(fmaxf(pw, 0.0f), IMGF));
        const float shp = sqrtf(fminf(fmaxf(ph, 0.0f), IMGF));
        const float dw = swp - sqrtf(fabsf(w));
        const float dh = shp - sqrtf(fabsf(h));
        contrib += 5.0f * (0.5f * dx * dx + 0.5f * dy * dy
                           + (0.5f * dw * dw) * (1.0f / IMGF)
                           + (0.5f * dh * dh) * (1.0f / IMGF));
    }
    contrib += __shfl_xor_sync(0xFFFFFFFFu, contrib, 1);
    contrib += __shfl_xor_sync(0xFFFFFFFFu, contrib, 2);
    contrib += __shfl_xor_sync(0xFFFFFFFFu, contrib, 4);

    if (valid && sub == 0)
        loss += 0.5f * cls + contrib;         // cls/contrib hold full group sums

    // block reduce -> one atomicAdd per block
    #pragma unroll
    for (int off = 16; off; off >>= 1)
        loss += __shfl_xor_sync(0xFFFFFFFFu, loss, off);
    if (lane == 0) swarp[wid] = loss;
    __syncthreads();
    if (tid == 0) {
        float s = 0.0f;
        #pragma unroll
        for (int i = 0; i < 8; i++) s += swarp[i];
        atomicAdd(&g_accum, s);
        __threadfence();
        s_last = (atomicAdd(&g_count, 1) == nblocks - 1);
    }
    __syncthreads();

    if (s_last && tid == 0) {
        __threadfence();
        out[0] = g_accum / (float)B;
        g_accum = 0.0f;                       // reset for next graph replay
        g_count = 0;
    }
}

extern "C" void kernel_launch(void* const* d_in, const int* in_sizes, int n_in,
                              void* d_out, int out_size)
{
    const float* predicts = (const float*)d_in[0];
    const float* labels   = (const float*)d_in[1];
    const int*   objnum   = (const int*)d_in[2];
    float* out = (float*)d_out;

    const int B = in_sizes[2];
    const int M = in_sizes[1] / (B * 5);
    const int ncells = B * CELLS2;

    const int gridA = ((ncells + 1) / 2 + 7) / 8;   // warp per 2 cells
    const int gridB = (B * M * 8 + 255) / 256;      // 8 threads per (b,o)

    stats_kernel<<<gridA, 256>>>(predicts, ncells);
    obj_kernel<<<gridB, 256>>>(predicts, labels, objnum, out, B, M, gridB);
}